// round 10
// baseline (speedup 1.0000x reference)
#include <cuda_runtime.h>
#include <cuda_bf16.h>
#include <cstdint>

// ---------------------------------------------------------------------------
// Problem constants
// ---------------------------------------------------------------------------
#define BATCH   128
#define CCH     256
#define HWSZ    784
#define KTOT    200704          // 256*784
#define CHUNK_K 64              // k per SMEM tile
#define NCHUNK  28              // chunks per CTA
#define GRIDX   112             // 112*28*64 = 200704
#define LDPAD   72              // bf16 elements per padded SMEM row (144 B)

// Device-global scratch (atomically accumulated; zeroed each call)
__device__ float g_gram[2][BATCH][BATCH];
__device__ float g_pool[2][BATCH][CCH];
__device__ float g_gate[2][BATCH][CCH];

// ---------------------------------------------------------------------------
// Helpers
// ---------------------------------------------------------------------------
__device__ __forceinline__ uint32_t smem_u32(const void* p) {
    uint32_t a;
    asm("{ .reg .u64 t; cvta.to.shared.u64 t, %1; cvt.u32.u64 %0, t; }"
        : "=r"(a) : "l"(p));
    return a;
}

__device__ __forceinline__ void ldmA(uint32_t a[4], uint32_t addr) {
    asm volatile("ldmatrix.sync.aligned.m8n8.x4.shared.b16 {%0,%1,%2,%3}, [%4];"
        : "=r"(a[0]), "=r"(a[1]), "=r"(a[2]), "=r"(a[3]) : "r"(addr));
}
__device__ __forceinline__ void ldmB(uint32_t b[2], uint32_t addr) {
    asm volatile("ldmatrix.sync.aligned.m8n8.x2.shared.b16 {%0,%1}, [%2];"
        : "=r"(b[0]), "=r"(b[1]) : "r"(addr));
}
__device__ __forceinline__ void mma16816(float c[4], const uint32_t a[4],
                                         const uint32_t b[2]) {
    asm volatile(
        "mma.sync.aligned.m16n8k16.row.col.f32.bf16.bf16.f32 "
        "{%0,%1,%2,%3}, {%4,%5,%6,%7}, {%8,%9}, {%0,%1,%2,%3};"
        : "+f"(c[0]), "+f"(c[1]), "+f"(c[2]), "+f"(c[3])
        : "r"(a[0]), "r"(a[1]), "r"(a[2]), "r"(a[3]), "r"(b[0]), "r"(b[1]));
}

// ---------------------------------------------------------------------------
// Kernel 0: zero scratch
// ---------------------------------------------------------------------------
__global__ void zero_kernel() {
    int i = blockIdx.x * 256 + threadIdx.x;            // 65536 threads
    if (i < 2 * BATCH * BATCH) (&g_gram[0][0][0])[i] = 0.f;
    (&g_pool[0][0][0])[i] = 0.f;                       // exactly 65536 elems
}

// ---------------------------------------------------------------------------
// Kernel 1: Gram + fused pooling — EXACT R1 version (393us baseline).
//   grid (112, 2): blockIdx.y = matrix (0 student, 1 teacher)
//   Each CTA: 28 chunks of [128 rows x 64 k], bf16 tile used as BOTH A and B.
//   8 warps in 2x4 layout, each computing a 64x32 accumulator region.
// ---------------------------------------------------------------------------
__global__ __launch_bounds__(256, 2)
void gram_kernel(const float* __restrict__ s, const float* __restrict__ t) {
    __shared__ __nv_bfloat16 tile[BATCH][LDPAD];

    const int mat  = blockIdx.y;
    const float* F = mat ? t : s;
    const int tid  = threadIdx.x;
    const int lane = tid & 31;
    const int wid  = tid >> 5;
    const int mbase = (wid & 1) * 64;
    const int nbase = (wid >> 1) * 32;

    // load mapping: 2 threads per row, 8 float4 each (32 contiguous floats)
    const int row = tid >> 1;
    const int kq0 = (tid & 1) * 8;     // float4 index base within 16
    const float* rowp = F + (size_t)row * KTOT;
    const int k0 = blockIdx.x * (NCHUNK * CHUNK_K);

    float acc[4][4][4];
    #pragma unroll
    for (int mi = 0; mi < 4; mi++)
        #pragma unroll
        for (int ni = 0; ni < 4; ni++)
            #pragma unroll
            for (int r = 0; r < 4; r++) acc[mi][ni][r] = 0.f;

    // prefetched chunk, already converted to bf16 (16 regs)
    uint2 pf[8];
    float pacc = 0.f;
    int   pch  = (k0 + kq0 * 4) / HWSZ;

    // prefetch chunk 0 (with fused pooling in fp32)
    #pragma unroll
    for (int i = 0; i < 8; i++) {
        int q  = kq0 + i;
        int kk = k0 + q * 4;
        float4 v = *(const float4*)(rowp + kk);
        int ch = kk / HWSZ;                       // float4 never crosses channel
        if (ch != pch) { atomicAdd(&g_pool[mat][row][pch], pacc); pacc = 0.f; pch = ch; }
        pacc += (v.x + v.y) + (v.z + v.w);
        __nv_bfloat162 p0 = __float22bfloat162_rn(make_float2(v.x, v.y));
        __nv_bfloat162 p1 = __float22bfloat162_rn(make_float2(v.z, v.w));
        pf[i] = make_uint2(*(uint32_t*)&p0, *(uint32_t*)&p1);
    }

    const uint32_t sbase = smem_u32(&tile[0][0]);
    const int lb = lane & 15;

    for (int c = 0; c < NCHUNK; c++) {
        if (c) __syncthreads();                    // compute(c-1) done before overwrite
        // store prefetched bf16 chunk
        #pragma unroll
        for (int i = 0; i < 8; i++) {
            int q = kq0 + i;
            *(uint2*)&tile[row][q * 4] = pf[i];
        }
        __syncthreads();

        // prefetch next chunk -- LDGs in flight during MMA work
        if (c + 1 < NCHUNK) {
            int kbase = k0 + (c + 1) * CHUNK_K;
            #pragma unroll
            for (int i = 0; i < 8; i++) {
                int q  = kq0 + i;
                int kk = kbase + q * 4;
                float4 v = *(const float4*)(rowp + kk);
                int ch = kk / HWSZ;
                if (ch != pch) { atomicAdd(&g_pool[mat][row][pch], pacc); pacc = 0.f; pch = ch; }
                pacc += (v.x + v.y) + (v.z + v.w);
                __nv_bfloat162 p0 = __float22bfloat162_rn(make_float2(v.x, v.y));
                __nv_bfloat162 p1 = __float22bfloat162_rn(make_float2(v.z, v.w));
                pf[i] = make_uint2(*(uint32_t*)&p0, *(uint32_t*)&p1);
            }
        }

        // compute: 4 k-steps of 16
        #pragma unroll
        for (int ks = 0; ks < 4; ks++) {
            uint32_t afr[4][4], bfr[4][2];
            #pragma unroll
            for (int mi = 0; mi < 4; mi++) {
                int r = mbase + mi * 16 + (lane & 15);
                int col = ks * 16 + (lane >> 4) * 8;
                ldmA(afr[mi], sbase + (uint32_t)(r * LDPAD + col) * 2u);
            }
            #pragma unroll
            for (int ni = 0; ni < 4; ni++) {
                int r = nbase + ni * 8 + (lb & 7);
                int col = ks * 16 + (lb >> 3) * 8;
                ldmB(bfr[ni], sbase + (uint32_t)(r * LDPAD + col) * 2u);
            }
            #pragma unroll
            for (int mi = 0; mi < 4; mi++)
                #pragma unroll
                for (int ni = 0; ni < 4; ni++)
                    mma16816(acc[mi][ni], afr[mi], bfr[ni]);
        }
    }

    // flush pooling remainder
    atomicAdd(&g_pool[mat][row][pch], pacc);

    // epilogue: atomic-reduce partial G
    const int mrow = lane >> 2;
    const int ncol = 2 * (lane & 3);
    #pragma unroll
    for (int mi = 0; mi < 4; mi++) {
        #pragma unroll
        for (int ni = 0; ni < 4; ni++) {
            int m = mbase + mi * 16 + mrow;
            int n = nbase + ni * 8 + ncol;
            atomicAdd(&g_gram[mat][m][n],         acc[mi][ni][0]);
            atomicAdd(&g_gram[mat][m][n + 1],     acc[mi][ni][1]);
            atomicAdd(&g_gram[mat][m + 8][n],     acc[mi][ni][2]);
            atomicAdd(&g_gram[mat][m + 8][n + 1], acc[mi][ni][3]);
        }
    }
}

// ---------------------------------------------------------------------------
// Kernel 2: normalize + z + 6 MLPs -> gates. 32 CTAs x 4 batch rows.
// Warp-cooperative dot products (coalesced weight reads).
// ---------------------------------------------------------------------------
__device__ __forceinline__ float warp_sum(float v) {
    #pragma unroll
    for (int o = 16; o; o >>= 1) v += __shfl_xor_sync(0xFFFFFFFFu, v, o);
    return v;
}

__device__ __forceinline__ void run_mlp(
    const float* __restrict__ w1, const float* __restrict__ b1,
    const float* __restrict__ w2, const float* __restrict__ b2,
    const float* zin, int zstride, int din, int dh, int dout,
    float* hb /*[4][128] flat*/, float* gs /*[4][256] flat*/, int wid, int lane)
{
    for (int j = wid; j < dh; j += 8) {
        const float* wr = w1 + (size_t)j * din;
        float a0 = 0, a1 = 0, a2 = 0, a3 = 0;
        for (int i = lane; i < din; i += 32) {
            float w = wr[i];
            a0 += zin[i] * w;
            a1 += zin[zstride + i] * w;
            a2 += zin[2 * zstride + i] * w;
            a3 += zin[3 * zstride + i] * w;
        }
        a0 = warp_sum(a0); a1 = warp_sum(a1); a2 = warp_sum(a2); a3 = warp_sum(a3);
        if (lane == 0) {
            float b = b1[j];
            hb[0 * 128 + j] = fmaxf(a0 + b, 0.f);
            hb[1 * 128 + j] = fmaxf(a1 + b, 0.f);
            hb[2 * 128 + j] = fmaxf(a2 + b, 0.f);
            hb[3 * 128 + j] = fmaxf(a3 + b, 0.f);
        }
    }
    __syncthreads();
    for (int j = wid; j < dout; j += 8) {
        const float* wr = w2 + (size_t)j * dh;
        float a0 = 0, a1 = 0, a2 = 0, a3 = 0;
        for (int i = lane; i < dh; i += 32) {
            float w = wr[i];
            a0 += hb[0 * 128 + i] * w;
            a1 += hb[1 * 128 + i] * w;
            a2 += hb[2 * 128 + i] * w;
            a3 += hb[3 * 128 + i] * w;
        }
        a0 = warp_sum(a0); a1 = warp_sum(a1); a2 = warp_sum(a2); a3 = warp_sum(a3);
        if (lane == 0) {
            float b = b2[j];
            gs[0 * 256 + j] += 1.f / (1.f + expf(-(a0 + b)));
            gs[1 * 256 + j] += 1.f / (1.f + expf(-(a1 + b)));
            gs[2 * 256 + j] += 1.f / (1.f + expf(-(a2 + b)));
            gs[3 * 256 + j] += 1.f / (1.f + expf(-(a3 + b)));
        }
    }
    __syncthreads();
}

__global__ __launch_bounds__(256)
void mlp_kernel(
    const float* __restrict__ fs_w1,  const float* __restrict__ fs_b1,
    const float* __restrict__ fs_w2,  const float* __restrict__ fs_b2,
    const float* __restrict__ fsa_w1, const float* __restrict__ fsa_b1,
    const float* __restrict__ fsa_w2, const float* __restrict__ fsa_b2,
    const float* __restrict__ fsm_w1, const float* __restrict__ fsm_b1,
    const float* __restrict__ fsm_w2, const float* __restrict__ fsm_b2,
    const float* __restrict__ ft_w1,  const float* __restrict__ ft_b1,
    const float* __restrict__ ft_w2,  const float* __restrict__ ft_b2,
    const float* __restrict__ fta_w1, const float* __restrict__ fta_b1,
    const float* __restrict__ fta_w2, const float* __restrict__ fta_b2,
    const float* __restrict__ ftm_w1, const float* __restrict__ ftm_b1,
    const float* __restrict__ ftm_w2, const float* __restrict__ ftm_b2)
{
    __shared__ float ngs[4][128], ngt[4][128];
    __shared__ float zc[4][512];            // [zs | zt]
    __shared__ float za[4][256], zm[4][256];
    __shared__ float hbuf[4][128];
    __shared__ float gsum[2][4][256];
    __shared__ float redw[8];

    const int tid  = threadIdx.x;
    const int lane = tid & 31;
    const int wid  = tid >> 5;
    const int r0   = blockIdx.x * 4;
    const int half = tid >> 7;              // 0: student, 1: teacher
    const int b    = tid & 127;

    // Step 1: row-normalized Gram rows (both matrices in parallel)
    for (int r = 0; r < 4; r++) {
        int rowi = r0 + r;
        float v = g_gram[half][rowi][b];
        float ss = warp_sum(v * v);
        if (lane == 0) redw[wid] = ss;
        __syncthreads();
        float nrm = sqrtf(redw[half * 4 + 0] + redw[half * 4 + 1] +
                          redw[half * 4 + 2] + redw[half * 4 + 3]);
        float inv = 1.f / fmaxf(nrm, 1e-12f);
        if (half) ngt[r][b] = v * inv; else ngs[r][b] = v * inv;
        __syncthreads();
    }

    // Step 2: zs = normG_s @ y_s, zt = normG_t @ y_t  (thread = channel c)
    const float inv784 = 1.f / 784.f;
    const int c = tid;
    float zs0 = 0, zs1 = 0, zs2 = 0, zs3 = 0;
    for (int bb = 0; bb < 128; bb++) {
        float yv = g_pool[0][bb][c] * inv784;
        zs0 += ngs[0][bb] * yv; zs1 += ngs[1][bb] * yv;
        zs2 += ngs[2][bb] * yv; zs3 += ngs[3][bb] * yv;
    }
    float zt0 = 0, zt1 = 0, zt2 = 0, zt3 = 0;
    for (int bb = 0; bb < 128; bb++) {
        float yv = g_pool[1][bb][c] * inv784;
        zt0 += ngt[0][bb] * yv; zt1 += ngt[1][bb] * yv;
        zt2 += ngt[2][bb] * yv; zt3 += ngt[3][bb] * yv;
    }
    zc[0][c] = zs0; zc[1][c] = zs1; zc[2][c] = zs2; zc[3][c] = zs3;
    zc[0][256 + c] = zt0; zc[1][256 + c] = zt1; zc[2][256 + c] = zt2; zc[3][256 + c] = zt3;
    za[0][c] = zs0 + zt0; za[1][c] = zs1 + zt1; za[2][c] = zs2 + zt2; za[3][c] = zs3 + zt3;
    zm[0][c] = zs0 * zt0; zm[1][c] = zs1 * zt1; zm[2][c] = zs2 * zt2; zm[3][c] = zs3 * zt3;
    #pragma unroll
    for (int m = 0; m < 2; m++)
        #pragma unroll
        for (int r = 0; r < 4; r++) gsum[m][r][c] = 0.f;
    __syncthreads();

    // Step 3: six MLPs
    run_mlp(fs_w1,  fs_b1,  fs_w2,  fs_b2,  &zc[0][0], 512, 512, 128, 256,
            &hbuf[0][0], &gsum[0][0][0], wid, lane);
    run_mlp(fsa_w1, fsa_b1, fsa_w2, fsa_b2, &za[0][0], 256, 256, 64, 256,
            &hbuf[0][0], &gsum[0][0][0], wid, lane);
    run_mlp(fsm_w1, fsm_b1, fsm_w2, fsm_b2, &zm[0][0], 256, 256, 64, 256,
            &hbuf[0][0], &gsum[0][0][0], wid, lane);
    run_mlp(ft_w1,  ft_b1,  ft_w2,  ft_b2,  &zc[0][0], 512, 512, 128, 256,
            &hbuf[0][0], &gsum[1][0][0], wid, lane);
    run_mlp(fta_w1, fta_b1, fta_w2, fta_b2, &za[0][0], 256, 256, 64, 256,
            &hbuf[0][0], &gsum[1][0][0], wid, lane);
    run_mlp(ftm_w1, ftm_b1, ftm_w2, ftm_b2, &zm[0][0], 256, 256, 64, 256,
            &hbuf[0][0], &gsum[1][0][0], wid, lane);

    // Step 4: write gates
    #pragma unroll
    for (int m = 0; m < 2; m++)
        #pragma unroll
        for (int r = 0; r < 4; r++)
            g_gate[m][r0 + r][c] = gsum[m][r][c];
}

// ---------------------------------------------------------------------------
// Kernel 3: out = gate ⊙ x  (both tensors; float4 granularity)
// ---------------------------------------------------------------------------
#define PERQ 6422528            // float4 per tensor (128*256*784/4)
__global__ __launch_bounds__(256)
void scale_kernel(const float4* __restrict__ s, const float4* __restrict__ t,
                  float4* __restrict__ out) {
    unsigned idx = blockIdx.x * 256u + threadIdx.x;    // 0 .. 12845055
    int m = idx >= PERQ;
    unsigned j = idx - (unsigned)m * PERQ;
    unsigned bc = j / 196u;                            // 196 float4 per (b,c)
    float g = g_gate[m][bc >> 8][bc & 255];
    float4 v = m ? t[j] : s[j];
    out[idx] = make_float4(g * v.x, g * v.y, g * v.z, g * v.w);
}

// ---------------------------------------------------------------------------
// Launch
// ---------------------------------------------------------------------------
extern "C" void kernel_launch(void* const* d_in, const int* in_sizes, int n_in,
                              void* d_out, int out_size) {
    const float* s = (const float*)d_in[0];
    const float* t = (const float*)d_in[1];
    const float* w[24];
    for (int i = 0; i < 24; i++) w[i] = (const float*)d_in[2 + i];

    zero_kernel<<<256, 256>>>();
    gram_kernel<<<dim3(GRIDX, 2), 256>>>(s, t);
    mlp_kernel<<<32, 256>>>(
        w[0],  w[1],  w[2],  w[3],
        w[4],  w[5],  w[6],  w[7],
        w[8],  w[9],  w[10], w[11],
        w[12], w[13], w[14], w[15],
        w[16], w[17], w[18], w[19],
        w[20], w[21], w[22], w[23]);
    scale_kernel<<<(2 * PERQ) / 256, 256>>>((const float4*)s, (const float4*)t,
                                            (float4*)d_out);
}

// round 13
// speedup vs baseline: 1.0695x; 1.0695x over previous
#include <cuda_runtime.h>
#include <cuda_bf16.h>
#include <cstdint>

// ---------------------------------------------------------------------------
// Problem constants
// ---------------------------------------------------------------------------
#define BATCH   128
#define CCH     256
#define HWSZ    784
#define KTOT    200704          // 256*784
#define CHUNK_K 64              // k per SMEM tile
#define NCHUNK  28              // chunks per CTA
#define GRIDX   112             // 112*28*64 = 200704
#define LDPAD   72              // bf16 elements per padded SMEM row (144 B)

// Device-global scratch (atomically accumulated; zeroed each call)
__device__ float g_gram[2][BATCH][BATCH];
__device__ float g_pool[2][BATCH][CCH];
__device__ float g_gate[2][BATCH][CCH];

// ---------------------------------------------------------------------------
// Helpers
// ---------------------------------------------------------------------------
__device__ __forceinline__ uint32_t smem_u32(const void* p) {
    uint32_t a;
    asm("{ .reg .u64 t; cvta.to.shared.u64 t, %1; cvt.u32.u64 %0, t; }"
        : "=r"(a) : "l"(p));
    return a;
}

__device__ __forceinline__ void ldmA(uint32_t a[4], uint32_t addr) {
    asm volatile("ldmatrix.sync.aligned.m8n8.x4.shared.b16 {%0,%1,%2,%3}, [%4];"
        : "=r"(a[0]), "=r"(a[1]), "=r"(a[2]), "=r"(a[3]) : "r"(addr));
}
__device__ __forceinline__ void ldmB(uint32_t b[2], uint32_t addr) {
    asm volatile("ldmatrix.sync.aligned.m8n8.x2.shared.b16 {%0,%1}, [%2];"
        : "=r"(b[0]), "=r"(b[1]) : "r"(addr));
}
__device__ __forceinline__ void mma16816(float c[4], const uint32_t a[4],
                                         const uint32_t b[2]) {
    asm volatile(
        "mma.sync.aligned.m16n8k16.row.col.f32.bf16.bf16.f32 "
        "{%0,%1,%2,%3}, {%4,%5,%6,%7}, {%8,%9}, {%0,%1,%2,%3};"
        : "+f"(c[0]), "+f"(c[1]), "+f"(c[2]), "+f"(c[3])
        : "r"(a[0]), "r"(a[1]), "r"(a[2]), "r"(a[3]), "r"(b[0]), "r"(b[1]));
}

// ---------------------------------------------------------------------------
// Kernel 0: zero scratch
// ---------------------------------------------------------------------------
__global__ void zero_kernel() {
    int i = blockIdx.x * 256 + threadIdx.x;            // 65536 threads
    if (i < 2 * BATCH * BATCH) (&g_gram[0][0][0])[i] = 0.f;
    (&g_pool[0][0][0])[i] = 0.f;                       // exactly 65536 elems
}

// ---------------------------------------------------------------------------
// Kernel 1: Gram + fused pooling — EXACT R1 version (393us baseline).
//   grid (112, 2): blockIdx.y = matrix (0 student, 1 teacher)
//   Each CTA: 28 chunks of [128 rows x 64 k], bf16 tile used as BOTH A and B.
//   8 warps in 2x4 layout, each computing a 64x32 accumulator region.
// ---------------------------------------------------------------------------
__global__ __launch_bounds__(256, 2)
void gram_kernel(const float* __restrict__ s, const float* __restrict__ t) {
    __shared__ __nv_bfloat16 tile[BATCH][LDPAD];

    const int mat  = blockIdx.y;
    const float* F = mat ? t : s;
    const int tid  = threadIdx.x;
    const int lane = tid & 31;
    const int wid  = tid >> 5;
    const int mbase = (wid & 1) * 64;
    const int nbase = (wid >> 1) * 32;

    // load mapping: 2 threads per row, 8 float4 each (32 contiguous floats)
    const int row = tid >> 1;
    const int kq0 = (tid & 1) * 8;     // float4 index base within 16
    const float* rowp = F + (size_t)row * KTOT;
    const int k0 = blockIdx.x * (NCHUNK * CHUNK_K);

    float acc[4][4][4];
    #pragma unroll
    for (int mi = 0; mi < 4; mi++)
        #pragma unroll
        for (int ni = 0; ni < 4; ni++)
            #pragma unroll
            for (int r = 0; r < 4; r++) acc[mi][ni][r] = 0.f;

    // prefetched chunk, already converted to bf16 (16 regs)
    uint2 pf[8];
    float pacc = 0.f;
    int   pch  = (k0 + kq0 * 4) / HWSZ;

    // prefetch chunk 0 (with fused pooling in fp32)
    #pragma unroll
    for (int i = 0; i < 8; i++) {
        int q  = kq0 + i;
        int kk = k0 + q * 4;
        float4 v = *(const float4*)(rowp + kk);
        int ch = kk / HWSZ;                       // float4 never crosses channel
        if (ch != pch) { atomicAdd(&g_pool[mat][row][pch], pacc); pacc = 0.f; pch = ch; }
        pacc += (v.x + v.y) + (v.z + v.w);
        __nv_bfloat162 p0 = __float22bfloat162_rn(make_float2(v.x, v.y));
        __nv_bfloat162 p1 = __float22bfloat162_rn(make_float2(v.z, v.w));
        pf[i] = make_uint2(*(uint32_t*)&p0, *(uint32_t*)&p1);
    }

    const uint32_t sbase = smem_u32(&tile[0][0]);
    const int lb = lane & 15;

    for (int c = 0; c < NCHUNK; c++) {
        if (c) __syncthreads();                    // compute(c-1) done before overwrite
        // store prefetched bf16 chunk
        #pragma unroll
        for (int i = 0; i < 8; i++) {
            int q = kq0 + i;
            *(uint2*)&tile[row][q * 4] = pf[i];
        }
        __syncthreads();

        // prefetch next chunk -- LDGs in flight during MMA work
        if (c + 1 < NCHUNK) {
            int kbase = k0 + (c + 1) * CHUNK_K;
            #pragma unroll
            for (int i = 0; i < 8; i++) {
                int q  = kq0 + i;
                int kk = kbase + q * 4;
                float4 v = *(const float4*)(rowp + kk);
                int ch = kk / HWSZ;
                if (ch != pch) { atomicAdd(&g_pool[mat][row][pch], pacc); pacc = 0.f; pch = ch; }
                pacc += (v.x + v.y) + (v.z + v.w);
                __nv_bfloat162 p0 = __float22bfloat162_rn(make_float2(v.x, v.y));
                __nv_bfloat162 p1 = __float22bfloat162_rn(make_float2(v.z, v.w));
                pf[i] = make_uint2(*(uint32_t*)&p0, *(uint32_t*)&p1);
            }
        }

        // compute: 4 k-steps of 16
        #pragma unroll
        for (int ks = 0; ks < 4; ks++) {
            uint32_t afr[4][4], bfr[4][2];
            #pragma unroll
            for (int mi = 0; mi < 4; mi++) {
                int r = mbase + mi * 16 + (lane & 15);
                int col = ks * 16 + (lane >> 4) * 8;
                ldmA(afr[mi], sbase + (uint32_t)(r * LDPAD + col) * 2u);
            }
            #pragma unroll
            for (int ni = 0; ni < 4; ni++) {
                int r = nbase + ni * 8 + (lb & 7);
                int col = ks * 16 + (lb >> 3) * 8;
                ldmB(bfr[ni], sbase + (uint32_t)(r * LDPAD + col) * 2u);
            }
            #pragma unroll
            for (int mi = 0; mi < 4; mi++)
                #pragma unroll
                for (int ni = 0; ni < 4; ni++)
                    mma16816(acc[mi][ni], afr[mi], bfr[ni]);
        }
    }

    // flush pooling remainder
    atomicAdd(&g_pool[mat][row][pch], pacc);

    // epilogue: atomic-reduce partial G
    const int mrow = lane >> 2;
    const int ncol = 2 * (lane & 3);
    #pragma unroll
    for (int mi = 0; mi < 4; mi++) {
        #pragma unroll
        for (int ni = 0; ni < 4; ni++) {
            int m = mbase + mi * 16 + mrow;
            int n = nbase + ni * 8 + ncol;
            atomicAdd(&g_gram[mat][m][n],         acc[mi][ni][0]);
            atomicAdd(&g_gram[mat][m][n + 1],     acc[mi][ni][1]);
            atomicAdd(&g_gram[mat][m + 8][n],     acc[mi][ni][2]);
            atomicAdd(&g_gram[mat][m + 8][n + 1], acc[mi][ni][3]);
        }
    }
}

// ---------------------------------------------------------------------------
// Kernel 2: normalize + z + 6 MLPs -> gates. 32 CTAs x 4 batch rows.
// EXACT R1 version (thread-per-output-row dot products).
// ---------------------------------------------------------------------------
__device__ __forceinline__ void run_mlp(
    const float* __restrict__ w1, const float* __restrict__ b1,
    const float* __restrict__ w2, const float* __restrict__ b2,
    const float* zin, int zstride, int din, int dh, int dout,
    float* hb /*[4][128] flat*/, float* gs /*[4][256] flat*/, int tid)
{
    if (tid < dh) {
        float a0 = b1[tid], a1 = b1[tid], a2 = b1[tid], a3 = b1[tid];
        const float* wrow = w1 + (size_t)tid * din;
        for (int i = 0; i < din; i++) {
            float w = wrow[i];
            a0 += zin[0 * zstride + i] * w;
            a1 += zin[1 * zstride + i] * w;
            a2 += zin[2 * zstride + i] * w;
            a3 += zin[3 * zstride + i] * w;
        }
        hb[0 * 128 + tid] = fmaxf(a0, 0.f);
        hb[1 * 128 + tid] = fmaxf(a1, 0.f);
        hb[2 * 128 + tid] = fmaxf(a2, 0.f);
        hb[3 * 128 + tid] = fmaxf(a3, 0.f);
    }
    __syncthreads();
    if (tid < dout) {
        float a0 = b2[tid], a1 = b2[tid], a2 = b2[tid], a3 = b2[tid];
        const float* wrow = w2 + (size_t)tid * dh;
        for (int i = 0; i < dh; i++) {
            float w = wrow[i];
            a0 += hb[0 * 128 + i] * w;
            a1 += hb[1 * 128 + i] * w;
            a2 += hb[2 * 128 + i] * w;
            a3 += hb[3 * 128 + i] * w;
        }
        gs[0 * 256 + tid] += 1.f / (1.f + expf(-a0));
        gs[1 * 256 + tid] += 1.f / (1.f + expf(-a1));
        gs[2 * 256 + tid] += 1.f / (1.f + expf(-a2));
        gs[3 * 256 + tid] += 1.f / (1.f + expf(-a3));
    }
    __syncthreads();
}

__global__ __launch_bounds__(256)
void mlp_kernel(
    const float* __restrict__ fs_w1,  const float* __restrict__ fs_b1,
    const float* __restrict__ fs_w2,  const float* __restrict__ fs_b2,
    const float* __restrict__ fsa_w1, const float* __restrict__ fsa_b1,
    const float* __restrict__ fsa_w2, const float* __restrict__ fsa_b2,
    const float* __restrict__ fsm_w1, const float* __restrict__ fsm_b1,
    const float* __restrict__ fsm_w2, const float* __restrict__ fsm_b2,
    const float* __restrict__ ft_w1,  const float* __restrict__ ft_b1,
    const float* __restrict__ ft_w2,  const float* __restrict__ ft_b2,
    const float* __restrict__ fta_w1, const float* __restrict__ fta_b1,
    const float* __restrict__ fta_w2, const float* __restrict__ fta_b2,
    const float* __restrict__ ftm_w1, const float* __restrict__ ftm_b1,
    const float* __restrict__ ftm_w2, const float* __restrict__ ftm_b2)
{
    __shared__ float ngs[4][128], ngt[4][128];
    __shared__ float zc[4][512];            // [zs | zt]
    __shared__ float za[4][256], zm[4][256];
    __shared__ float hbuf[4][128];
    __shared__ float gsum[2][4][256];
    __shared__ float redw[8];

    const int tid  = threadIdx.x;
    const int r0   = blockIdx.x * 4;
    const int half = tid >> 7;              // 0: student, 1: teacher
    const int b    = tid & 127;

    // Step 1: row-normalized Gram rows for our 4 rows (both matrices in parallel)
    for (int r = 0; r < 4; r++) {
        int rowi = r0 + r;
        float v = g_gram[half][rowi][b];
        float ss = v * v;
        #pragma unroll
        for (int o = 16; o; o >>= 1) ss += __shfl_xor_sync(0xFFFFFFFFu, ss, o);
        if ((tid & 31) == 0) redw[tid >> 5] = ss;
        __syncthreads();
        float nrm = sqrtf(redw[half * 4 + 0] + redw[half * 4 + 1] +
                          redw[half * 4 + 2] + redw[half * 4 + 3]);
        float inv = 1.f / fmaxf(nrm, 1e-12f);
        if (half) ngt[r][b] = v * inv; else ngs[r][b] = v * inv;
        __syncthreads();
    }

    // Step 2: zs = normG_s @ y_s, zt = normG_t @ y_t  (thread = channel c)
    const float inv784 = 1.f / 784.f;
    const int c = tid;
    float zs0 = 0, zs1 = 0, zs2 = 0, zs3 = 0;
    for (int bb = 0; bb < 128; bb++) {
        float yv = g_pool[0][bb][c] * inv784;
        zs0 += ngs[0][bb] * yv; zs1 += ngs[1][bb] * yv;
        zs2 += ngs[2][bb] * yv; zs3 += ngs[3][bb] * yv;
    }
    float zt0 = 0, zt1 = 0, zt2 = 0, zt3 = 0;
    for (int bb = 0; bb < 128; bb++) {
        float yv = g_pool[1][bb][c] * inv784;
        zt0 += ngt[0][bb] * yv; zt1 += ngt[1][bb] * yv;
        zt2 += ngt[2][bb] * yv; zt3 += ngt[3][bb] * yv;
    }
    zc[0][c] = zs0; zc[1][c] = zs1; zc[2][c] = zs2; zc[3][c] = zs3;
    zc[0][256 + c] = zt0; zc[1][256 + c] = zt1; zc[2][256 + c] = zt2; zc[3][256 + c] = zt3;
    za[0][c] = zs0 + zt0; za[1][c] = zs1 + zt1; za[2][c] = zs2 + zt2; za[3][c] = zs3 + zt3;
    zm[0][c] = zs0 * zt0; zm[1][c] = zs1 * zt1; zm[2][c] = zs2 * zt2; zm[3][c] = zs3 * zt3;
    #pragma unroll
    for (int m = 0; m < 2; m++)
        #pragma unroll
        for (int r = 0; r < 4; r++) gsum[m][r][c] = 0.f;
    __syncthreads();

    // Step 3: six MLPs
    run_mlp(fs_w1,  fs_b1,  fs_w2,  fs_b2,  &zc[0][0], 512, 512, 128, 256,
            &hbuf[0][0], &gsum[0][0][0], tid);
    run_mlp(fsa_w1, fsa_b1, fsa_w2, fsa_b2, &za[0][0], 256, 256, 64, 256,
            &hbuf[0][0], &gsum[0][0][0], tid);
    run_mlp(fsm_w1, fsm_b1, fsm_w2, fsm_b2, &zm[0][0], 256, 256, 64, 256,
            &hbuf[0][0], &gsum[0][0][0], tid);
    run_mlp(ft_w1,  ft_b1,  ft_w2,  ft_b2,  &zc[0][0], 512, 512, 128, 256,
            &hbuf[0][0], &gsum[1][0][0], tid);
    run_mlp(fta_w1, fta_b1, fta_w2, fta_b2, &za[0][0], 256, 256, 64, 256,
            &hbuf[0][0], &gsum[1][0][0], tid);
    run_mlp(ftm_w1, ftm_b1, ftm_w2, ftm_b2, &zm[0][0], 256, 256, 64, 256,
            &hbuf[0][0], &gsum[1][0][0], tid);

    // Step 4: write gates
    #pragma unroll
    for (int m = 0; m < 2; m++)
        #pragma unroll
        for (int r = 0; r < 4; r++)
            g_gate[m][r0 + r][c] = gsum[m][r][c];
}

// ---------------------------------------------------------------------------
// Kernel 3: out = gate ⊙ x  (both tensors; float4 granularity)
// ---------------------------------------------------------------------------
#define PERQ 6422528            // float4 per tensor (128*256*784/4)
__global__ __launch_bounds__(256)
void scale_kernel(const float4* __restrict__ s, const float4* __restrict__ t,
                  float4* __restrict__ out) {
    unsigned idx = blockIdx.x * 256u + threadIdx.x;    // 0 .. 12845055
    int m = idx >= PERQ;
    unsigned j = idx - (unsigned)m * PERQ;
    unsigned bc = j / 196u;                            // 196 float4 per (b,c)
    float g = g_gate[m][bc >> 8][bc & 255];
    float4 v = m ? t[j] : s[j];
    out[idx] = make_float4(g * v.x, g * v.y, g * v.z, g * v.w);
}

// ---------------------------------------------------------------------------
// Launch.  INSTRUMENTED this round: gram runs twice with a re-zero between
// (final state identical to a single run; the delta vs the 393us baseline
// measures gram_kernel directly, and gram lands in ncu's captured slot).
// ---------------------------------------------------------------------------
extern "C" void kernel_launch(void* const* d_in, const int* in_sizes, int n_in,
                              void* d_out, int out_size) {
    const float* s = (const float*)d_in[0];
    const float* t = (const float*)d_in[1];
    const float* w[24];
    for (int i = 0; i < 24; i++) w[i] = (const float*)d_in[2 + i];

    zero_kernel<<<256, 256>>>();                         // launch 1
    gram_kernel<<<dim3(GRIDX, 2), 256>>>(s, t);          // launch 2 (timed extra)
    zero_kernel<<<256, 256>>>();                         // launch 3 (reset state)
    gram_kernel<<<dim3(GRIDX, 2), 256>>>(s, t);          // launch 4 (the real one)
    mlp_kernel<<<32, 256>>>(
        w[0],  w[1],  w[2],  w[3],
        w[4],  w[5],  w[6],  w[7],
        w[8],  w[9],  w[10], w[11],
        w[12], w[13], w[14], w[15],
        w[16], w[17], w[18], w[19],
        w[20], w[21], w[22], w[23]);
    scale_kernel<<<(2 * PERQ) / 256, 256>>>((const float4*)s, (const float4*)t,
                                            (float4*)d_out);
}

// round 14
// speedup vs baseline: 2.5607x; 2.3943x over previous
#include <cuda_runtime.h>
#include <cuda_bf16.h>
#include <cstdint>

// ---------------------------------------------------------------------------
// Problem constants
// ---------------------------------------------------------------------------
#define BATCH   128
#define CCH     256
#define HWSZ    784
#define KTOT    200704          // 256*784
#define CHUNK_K 64              // k per SMEM tile
#define NCHUNK  28              // chunks per CTA
#define GRIDX   112             // 112*28*64 = 200704
#define LDPAD   72              // bf16 elements per padded SMEM row (144 B)

// Device-global scratch (atomically accumulated; zeroed each call)
__device__ float g_gram[2][BATCH][BATCH];
__device__ float g_pool[2][BATCH][CCH];
__device__ float g_gate[2][BATCH][CCH];

// ---------------------------------------------------------------------------
// Helpers
// ---------------------------------------------------------------------------
__device__ __forceinline__ uint32_t smem_u32(const void* p) {
    uint32_t a;
    asm("{ .reg .u64 t; cvta.to.shared.u64 t, %1; cvt.u32.u64 %0, t; }"
        : "=r"(a) : "l"(p));
    return a;
}

__device__ __forceinline__ void ldmA(uint32_t a[4], uint32_t addr) {
    asm volatile("ldmatrix.sync.aligned.m8n8.x4.shared.b16 {%0,%1,%2,%3}, [%4];"
        : "=r"(a[0]), "=r"(a[1]), "=r"(a[2]), "=r"(a[3]) : "r"(addr));
}
__device__ __forceinline__ void ldmB(uint32_t b[2], uint32_t addr) {
    asm volatile("ldmatrix.sync.aligned.m8n8.x2.shared.b16 {%0,%1}, [%2];"
        : "=r"(b[0]), "=r"(b[1]) : "r"(addr));
}
__device__ __forceinline__ void mma16816(float c[4], const uint32_t a[4],
                                         const uint32_t b[2]) {
    asm volatile(
        "mma.sync.aligned.m16n8k16.row.col.f32.bf16.bf16.f32 "
        "{%0,%1,%2,%3}, {%4,%5,%6,%7}, {%8,%9}, {%0,%1,%2,%3};"
        : "+f"(c[0]), "+f"(c[1]), "+f"(c[2]), "+f"(c[3])
        : "r"(a[0]), "r"(a[1]), "r"(a[2]), "r"(a[3]), "r"(b[0]), "r"(b[1]));
}

// ---------------------------------------------------------------------------
// Kernel 0: zero scratch (g_gram 32768 + g_pool 65536 + g_gate 65536 floats)
// ---------------------------------------------------------------------------
__global__ void zero_kernel() {
    int i = blockIdx.x * 256 + threadIdx.x;            // 65536 threads
    if (i < 2 * BATCH * BATCH) (&g_gram[0][0][0])[i] = 0.f;
    (&g_pool[0][0][0])[i] = 0.f;
    (&g_gate[0][0][0])[i] = 0.f;
}

// ---------------------------------------------------------------------------
// Kernel 1: Gram + fused pooling — EXACT R1 version (97us measured).
// ---------------------------------------------------------------------------
__global__ __launch_bounds__(256, 2)
void gram_kernel(const float* __restrict__ s, const float* __restrict__ t) {
    __shared__ __nv_bfloat16 tile[BATCH][LDPAD];

    const int mat  = blockIdx.y;
    const float* F = mat ? t : s;
    const int tid  = threadIdx.x;
    const int lane = tid & 31;
    const int wid  = tid >> 5;
    const int mbase = (wid & 1) * 64;
    const int nbase = (wid >> 1) * 32;

    const int row = tid >> 1;
    const int kq0 = (tid & 1) * 8;
    const float* rowp = F + (size_t)row * KTOT;
    const int k0 = blockIdx.x * (NCHUNK * CHUNK_K);

    float acc[4][4][4];
    #pragma unroll
    for (int mi = 0; mi < 4; mi++)
        #pragma unroll
        for (int ni = 0; ni < 4; ni++)
            #pragma unroll
            for (int r = 0; r < 4; r++) acc[mi][ni][r] = 0.f;

    uint2 pf[8];
    float pacc = 0.f;
    int   pch  = (k0 + kq0 * 4) / HWSZ;

    #pragma unroll
    for (int i = 0; i < 8; i++) {
        int q  = kq0 + i;
        int kk = k0 + q * 4;
        float4 v = *(const float4*)(rowp + kk);
        int ch = kk / HWSZ;
        if (ch != pch) { atomicAdd(&g_pool[mat][row][pch], pacc); pacc = 0.f; pch = ch; }
        pacc += (v.x + v.y) + (v.z + v.w);
        __nv_bfloat162 p0 = __float22bfloat162_rn(make_float2(v.x, v.y));
        __nv_bfloat162 p1 = __float22bfloat162_rn(make_float2(v.z, v.w));
        pf[i] = make_uint2(*(uint32_t*)&p0, *(uint32_t*)&p1);
    }

    const uint32_t sbase = smem_u32(&tile[0][0]);
    const int lb = lane & 15;

    for (int c = 0; c < NCHUNK; c++) {
        if (c) __syncthreads();
        #pragma unroll
        for (int i = 0; i < 8; i++) {
            int q = kq0 + i;
            *(uint2*)&tile[row][q * 4] = pf[i];
        }
        __syncthreads();

        if (c + 1 < NCHUNK) {
            int kbase = k0 + (c + 1) * CHUNK_K;
            #pragma unroll
            for (int i = 0; i < 8; i++) {
                int q  = kq0 + i;
                int kk = kbase + q * 4;
                float4 v = *(const float4*)(rowp + kk);
                int ch = kk / HWSZ;
                if (ch != pch) { atomicAdd(&g_pool[mat][row][pch], pacc); pacc = 0.f; pch = ch; }
                pacc += (v.x + v.y) + (v.z + v.w);
                __nv_bfloat162 p0 = __float22bfloat162_rn(make_float2(v.x, v.y));
                __nv_bfloat162 p1 = __float22bfloat162_rn(make_float2(v.z, v.w));
                pf[i] = make_uint2(*(uint32_t*)&p0, *(uint32_t*)&p1);
            }
        }

        #pragma unroll
        for (int ks = 0; ks < 4; ks++) {
            uint32_t afr[4][4], bfr[4][2];
            #pragma unroll
            for (int mi = 0; mi < 4; mi++) {
                int r = mbase + mi * 16 + (lane & 15);
                int col = ks * 16 + (lane >> 4) * 8;
                ldmA(afr[mi], sbase + (uint32_t)(r * LDPAD + col) * 2u);
            }
            #pragma unroll
            for (int ni = 0; ni < 4; ni++) {
                int r = nbase + ni * 8 + (lb & 7);
                int col = ks * 16 + (lb >> 3) * 8;
                ldmB(bfr[ni], sbase + (uint32_t)(r * LDPAD + col) * 2u);
            }
            #pragma unroll
            for (int mi = 0; mi < 4; mi++)
                #pragma unroll
                for (int ni = 0; ni < 4; ni++)
                    mma16816(acc[mi][ni], afr[mi], bfr[ni]);
        }
    }

    atomicAdd(&g_pool[mat][row][pch], pacc);

    const int mrow = lane >> 2;
    const int ncol = 2 * (lane & 3);
    #pragma unroll
    for (int mi = 0; mi < 4; mi++) {
        #pragma unroll
        for (int ni = 0; ni < 4; ni++) {
            int m = mbase + mi * 16 + mrow;
            int n = nbase + ni * 8 + ncol;
            atomicAdd(&g_gram[mat][m][n],         acc[mi][ni][0]);
            atomicAdd(&g_gram[mat][m][n + 1],     acc[mi][ni][1]);
            atomicAdd(&g_gram[mat][m + 8][n],     acc[mi][ni][2]);
            atomicAdd(&g_gram[mat][m + 8][n + 1], acc[mi][ni][3]);
        }
    }
}

// ---------------------------------------------------------------------------
// Kernel 2: normalize + z + ONE MLP per CTA -> atomicAdd into gates.
//   grid (32, 6): blockIdx.x = 4-row group, blockIdx.y = which MLP.
//   Templated dims -> unrolled, float4 weight loads.
// ---------------------------------------------------------------------------
template <int DIN, int DH, int DOUT, int MAT>
__device__ __forceinline__ void run_mlp2(
    const float* __restrict__ w1, const float* __restrict__ b1,
    const float* __restrict__ w2, const float* __restrict__ b2,
    const float* zin /*[4][zstride]*/, int zstride,
    float* hb /*[4][128] flat*/, int r0, int tid)
{
    if (tid < DH) {
        const float4* wr = (const float4*)(w1 + (size_t)tid * DIN);
        float a0 = b1[tid], a1 = a0, a2 = a0, a3 = a0;
        a1 = b1[tid]; a2 = b1[tid]; a3 = b1[tid];
        #pragma unroll 8
        for (int i4 = 0; i4 < DIN / 4; i4++) {
            float4 w = wr[i4];
            const float* z0 = zin + 4 * i4;
            a0 += z0[0] * w.x + z0[1] * w.y + z0[2] * w.z + z0[3] * w.w;
            const float* z1 = z0 + zstride;
            a1 += z1[0] * w.x + z1[1] * w.y + z1[2] * w.z + z1[3] * w.w;
            const float* z2 = z1 + zstride;
            a2 += z2[0] * w.x + z2[1] * w.y + z2[2] * w.z + z2[3] * w.w;
            const float* z3 = z2 + zstride;
            a3 += z3[0] * w.x + z3[1] * w.y + z3[2] * w.z + z3[3] * w.w;
        }
        hb[0 * 128 + tid] = fmaxf(a0, 0.f);
        hb[1 * 128 + tid] = fmaxf(a1, 0.f);
        hb[2 * 128 + tid] = fmaxf(a2, 0.f);
        hb[3 * 128 + tid] = fmaxf(a3, 0.f);
    }
    __syncthreads();
    {
        const float4* wr = (const float4*)(w2 + (size_t)tid * DH);
        float a0 = b2[tid], a1 = b2[tid], a2 = b2[tid], a3 = b2[tid];
        #pragma unroll 8
        for (int i4 = 0; i4 < DH / 4; i4++) {
            float4 w = wr[i4];
            const float* h0 = hb + 4 * i4;
            a0 += h0[0] * w.x + h0[1] * w.y + h0[2] * w.z + h0[3] * w.w;
            const float* h1 = h0 + 128;
            a1 += h1[0] * w.x + h1[1] * w.y + h1[2] * w.z + h1[3] * w.w;
            const float* h2 = h1 + 128;
            a2 += h2[0] * w.x + h2[1] * w.y + h2[2] * w.z + h2[3] * w.w;
            const float* h3 = h2 + 128;
            a3 += h3[0] * w.x + h3[1] * w.y + h3[2] * w.z + h3[3] * w.w;
        }
        // relu(sigmoid(x)) == sigmoid(x); gates sum three sigmoids
        atomicAdd(&g_gate[MAT][r0 + 0][tid], 1.f / (1.f + expf(-a0)));
        atomicAdd(&g_gate[MAT][r0 + 1][tid], 1.f / (1.f + expf(-a1)));
        atomicAdd(&g_gate[MAT][r0 + 2][tid], 1.f / (1.f + expf(-a2)));
        atomicAdd(&g_gate[MAT][r0 + 3][tid], 1.f / (1.f + expf(-a3)));
    }
}

__global__ __launch_bounds__(256)
void mlp_kernel(
    const float* __restrict__ fs_w1,  const float* __restrict__ fs_b1,
    const float* __restrict__ fs_w2,  const float* __restrict__ fs_b2,
    const float* __restrict__ fsa_w1, const float* __restrict__ fsa_b1,
    const float* __restrict__ fsa_w2, const float* __restrict__ fsa_b2,
    const float* __restrict__ fsm_w1, const float* __restrict__ fsm_b1,
    const float* __restrict__ fsm_w2, const float* __restrict__ fsm_b2,
    const float* __restrict__ ft_w1,  const float* __restrict__ ft_b1,
    const float* __restrict__ ft_w2,  const float* __restrict__ ft_b2,
    const float* __restrict__ fta_w1, const float* __restrict__ fta_b1,
    const float* __restrict__ fta_w2, const float* __restrict__ fta_b2,
    const float* __restrict__ ftm_w1, const float* __restrict__ ftm_b1,
    const float* __restrict__ ftm_w2, const float* __restrict__ ftm_b2)
{
    __shared__ float ngs[4][128], ngt[4][128];
    __shared__ float zc[4][512];            // [zs | zt]
    __shared__ float za[4][256], zm[4][256];
    __shared__ float hbuf[4][128];
    __shared__ float redw[8];

    const int tid  = threadIdx.x;
    const int r0   = blockIdx.x * 4;
    const int half = tid >> 7;              // 0: student, 1: teacher
    const int b    = tid & 127;

    // Step 1: row-normalized Gram rows for our 4 rows (both matrices in parallel)
    for (int r = 0; r < 4; r++) {
        int rowi = r0 + r;
        float v = g_gram[half][rowi][b];
        float ss = v * v;
        #pragma unroll
        for (int o = 16; o; o >>= 1) ss += __shfl_xor_sync(0xFFFFFFFFu, ss, o);
        if ((tid & 31) == 0) redw[tid >> 5] = ss;
        __syncthreads();
        float nrm = sqrtf(redw[half * 4 + 0] + redw[half * 4 + 1] +
                          redw[half * 4 + 2] + redw[half * 4 + 3]);
        float inv = 1.f / fmaxf(nrm, 1e-12f);
        if (half) ngt[r][b] = v * inv; else ngs[r][b] = v * inv;
        __syncthreads();
    }

    // Step 2: zs = normG_s @ y_s, zt = normG_t @ y_t  (thread = channel c)
    const float inv784 = 1.f / 784.f;
    const int c = tid;
    float zs0 = 0, zs1 = 0, zs2 = 0, zs3 = 0;
    for (int bb = 0; bb < 128; bb++) {
        float yv = g_pool[0][bb][c] * inv784;
        zs0 += ngs[0][bb] * yv; zs1 += ngs[1][bb] * yv;
        zs2 += ngs[2][bb] * yv; zs3 += ngs[3][bb] * yv;
    }
    float zt0 = 0, zt1 = 0, zt2 = 0, zt3 = 0;
    for (int bb = 0; bb < 128; bb++) {
        float yv = g_pool[1][bb][c] * inv784;
        zt0 += ngt[0][bb] * yv; zt1 += ngt[1][bb] * yv;
        zt2 += ngt[2][bb] * yv; zt3 += ngt[3][bb] * yv;
    }
    zc[0][c] = zs0; zc[1][c] = zs1; zc[2][c] = zs2; zc[3][c] = zs3;
    zc[0][256 + c] = zt0; zc[1][256 + c] = zt1; zc[2][256 + c] = zt2; zc[3][256 + c] = zt3;
    za[0][c] = zs0 + zt0; za[1][c] = zs1 + zt1; za[2][c] = zs2 + zt2; za[3][c] = zs3 + zt3;
    zm[0][c] = zs0 * zt0; zm[1][c] = zs1 * zt1; zm[2][c] = zs2 * zt2; zm[3][c] = zs3 * zt3;
    __syncthreads();

    // Step 3: one MLP per CTA (blockIdx.y selects)
    switch (blockIdx.y) {
    case 0: run_mlp2<512, 128, 256, 0>(fs_w1, fs_b1, fs_w2, fs_b2,
                &zc[0][0], 512, &hbuf[0][0], r0, tid); break;
    case 1: run_mlp2<256, 64, 256, 0>(fsa_w1, fsa_b1, fsa_w2, fsa_b2,
                &za[0][0], 256, &hbuf[0][0], r0, tid); break;
    case 2: run_mlp2<256, 64, 256, 0>(fsm_w1, fsm_b1, fsm_w2, fsm_b2,
                &zm[0][0], 256, &hbuf[0][0], r0, tid); break;
    case 3: run_mlp2<512, 128, 256, 1>(ft_w1, ft_b1, ft_w2, ft_b2,
                &zc[0][0], 512, &hbuf[0][0], r0, tid); break;
    case 4: run_mlp2<256, 64, 256, 1>(fta_w1, fta_b1, fta_w2, fta_b2,
                &za[0][0], 256, &hbuf[0][0], r0, tid); break;
    case 5: run_mlp2<256, 64, 256, 1>(ftm_w1, ftm_b1, ftm_w2, ftm_b2,
                &zm[0][0], 256, &hbuf[0][0], r0, tid); break;
    }
}

// ---------------------------------------------------------------------------
// Kernel 3: out = gate ⊙ x  (both tensors; float4 granularity)
// ---------------------------------------------------------------------------
#define PERQ 6422528            // float4 per tensor (128*256*784/4)
__global__ __launch_bounds__(256)
void scale_kernel(const float4* __restrict__ s, const float4* __restrict__ t,
                  float4* __restrict__ out) {
    unsigned idx = blockIdx.x * 256u + threadIdx.x;    // 0 .. 12845055
    int m = idx >= PERQ;
    unsigned j = idx - (unsigned)m * PERQ;
    unsigned bc = j / 196u;                            // 196 float4 per (b,c)
    float g = g_gate[m][bc >> 8][bc & 255];
    float4 v = m ? t[j] : s[j];
    out[idx] = make_float4(g * v.x, g * v.y, g * v.z, g * v.w);
}

// ---------------------------------------------------------------------------
// Launch
// ---------------------------------------------------------------------------
extern "C" void kernel_launch(void* const* d_in, const int* in_sizes, int n_in,
                              void* d_out, int out_size) {
    const float* s = (const float*)d_in[0];
    const float* t = (const float*)d_in[1];
    const float* w[24];
    for (int i = 0; i < 24; i++) w[i] = (const float*)d_in[2 + i];

    zero_kernel<<<256, 256>>>();
    gram_kernel<<<dim3(GRIDX, 2), 256>>>(s, t);
    mlp_kernel<<<dim3(32, 6), 256>>>(
        w[0],  w[1],  w[2],  w[3],
        w[4],  w[5],  w[6],  w[7],
        w[8],  w[9],  w[10], w[11],
        w[12], w[13], w[14], w[15],
        w[16], w[17], w[18], w[19],
        w[20], w[21], w[22], w[23]);
    scale_kernel<<<(2 * PERQ) / 256, 256>>>((const float4*)s, (const float4*)t,
                                            (float4*)d_out);
}

// round 15
// speedup vs baseline: 2.9431x; 1.1493x over previous
#include <cuda_runtime.h>
#include <cuda_bf16.h>
#include <cstdint>

// ---------------------------------------------------------------------------
// Problem constants
// ---------------------------------------------------------------------------
#define BATCH   128
#define CCH     256
#define HWSZ    784
#define KTOT    200704          // 256*784
#define CHUNK_K 64              // fp32 elements per row per chunk
#define TOTCH   3136            // KTOT / 64
#define GRIDX   148             // 28 CTAs take 22 chunks, 120 take 21
#define LDPAD   72              // bf16 per padded SMEM row (144 B)

// Device-global scratch (zeroed / overwritten each call)
__device__ float g_gram[2][BATCH][BATCH];
__device__ float g_pool[2][BATCH][CCH];
__device__ float g_gate[2][BATCH][CCH];
__device__ float g_zs[BATCH][CCH];
__device__ float g_zt[BATCH][CCH];

// ---------------------------------------------------------------------------
// Helpers
// ---------------------------------------------------------------------------
__device__ __forceinline__ uint32_t smem_u32(const void* p) {
    uint32_t a;
    asm("{ .reg .u64 t; cvta.to.shared.u64 t, %1; cvt.u32.u64 %0, t; }"
        : "=r"(a) : "l"(p));
    return a;
}
__device__ __forceinline__ void ldm4(uint32_t a[4], uint32_t addr) {
    asm volatile("ldmatrix.sync.aligned.m8n8.x4.shared.b16 {%0,%1,%2,%3}, [%4];"
        : "=r"(a[0]), "=r"(a[1]), "=r"(a[2]), "=r"(a[3]) : "r"(addr));
}
__device__ __forceinline__ void mma16816(float c[4], const uint32_t a[4],
                                         const uint32_t b0, const uint32_t b1) {
    asm volatile(
        "mma.sync.aligned.m16n8k16.row.col.f32.bf16.bf16.f32 "
        "{%0,%1,%2,%3}, {%4,%5,%6,%7}, {%8,%9}, {%0,%1,%2,%3};"
        : "+f"(c[0]), "+f"(c[1]), "+f"(c[2]), "+f"(c[3])
        : "r"(a[0]), "r"(a[1]), "r"(a[2]), "r"(a[3]), "r"(b0), "r"(b1));
}
__device__ __forceinline__ uint2 cvt_bf16x4(float4 v) {
    __nv_bfloat162 p0 = __float22bfloat162_rn(make_float2(v.x, v.y));
    __nv_bfloat162 p1 = __float22bfloat162_rn(make_float2(v.z, v.w));
    return make_uint2(*(uint32_t*)&p0, *(uint32_t*)&p1);
}

// ---------------------------------------------------------------------------
// Kernel 0: zero scratch (g_gram + g_pool + g_gate)
// ---------------------------------------------------------------------------
__global__ void zero_kernel() {
    int i = blockIdx.x * 256 + threadIdx.x;            // 65536 threads
    if (i < 2 * BATCH * BATCH) (&g_gram[0][0][0])[i] = 0.f;
    (&g_pool[0][0][0])[i] = 0.f;
    (&g_gate[0][0][0])[i] = 0.f;
}

// ---------------------------------------------------------------------------
// Kernel 1: Gram + fused pooling — R6 version (~70us: measured -27 vs R1
//   via the R10/R6 controlled pair).
//   grid (148, 2). CTA: 21-22 CONTIGUOUS chunks of [128 rows x 64 fp32].
//   Coalesced loads (nL=4/LDG): lanes 0-15 one row segment, 16-31 the next;
//   thread owns rows {w*16 + h + 2i}, one shared channel register.
//   Compute: warp w rows (w&1)*64..+64 x cols (w>>1)*32..+32,
//   per k-step: 4 ldm4 (A) + 2 ldm4 (B) + 16 MMAs.
// ---------------------------------------------------------------------------
__global__ __launch_bounds__(256, 2)
void gram_kernel(const float* __restrict__ s, const float* __restrict__ t) {
    __shared__ __nv_bfloat16 tile[BATCH][LDPAD];

    const int mat  = blockIdx.y;
    const float* F = mat ? t : s;
    const int tid  = threadIdx.x;
    const int lane = tid & 31;
    const int wid  = tid >> 5;
    const int h    = lane >> 4;
    const int li   = lane & 15;

    const int bx     = blockIdx.x;
    const int start  = bx * 21 + (bx < 28 ? bx : 28);
    const int nchunk = 21 + (bx < 28);

    const int   row0  = wid * 16 + h;
    const float* rbase = F + (size_t)row0 * KTOT + li * 4;

    float acc[4][4][4];
    #pragma unroll
    for (int mi = 0; mi < 4; mi++)
        #pragma unroll
        for (int ni = 0; ni < 4; ni++)
            #pragma unroll
            for (int r = 0; r < 4; r++) acc[mi][ni][r] = 0.f;

    float accP[8];
    #pragma unroll
    for (int i = 0; i < 8; i++) accP[i] = 0.f;
    int ch = (start * CHUNK_K + li * 4) / HWSZ;

    uint2 pf[8];

    // prefetch chunk 0 (2 batches of 4 LDG.128)
    {
        const int kb = start * CHUNK_K;
        #pragma unroll
        for (int g = 0; g < 2; g++) {
            float4 v[4];
            #pragma unroll
            for (int j = 0; j < 4; j++)
                v[j] = *(const float4*)(rbase + (size_t)(2 * (4 * g + j)) * KTOT + kb);
            #pragma unroll
            for (int j = 0; j < 4; j++) {
                accP[4 * g + j] += (v[j].x + v[j].y) + (v[j].z + v[j].w);
                pf[4 * g + j] = cvt_bf16x4(v[j]);
            }
        }
    }

    const int mbase = (wid & 1) * 64;
    const int nbase = (wid >> 1) * 32;
    const int a_row  = lane & 15;
    const int a_colo = (lane >> 4) * 8;
    const int bq     = lane >> 3;
    const int b_rowo = ((bq >> 1) & 1) * 8 + (lane & 7);
    const int b_colo = (bq & 1) * 8;

    for (int c = 0; c < nchunk; c++) {
        #pragma unroll
        for (int i = 0; i < 8; i++)
            *(uint2*)&tile[row0 + 2 * i][li * 4] = pf[i];
        __syncthreads();

        if (c + 1 < nchunk) {
            const int kb  = (start + c + 1) * CHUNK_K;
            const int nch = (kb + li * 4) / HWSZ;
            if (nch != ch) {
                #pragma unroll
                for (int i = 0; i < 8; i++) {
                    atomicAdd(&g_pool[mat][row0 + 2 * i][ch], accP[i]);
                    accP[i] = 0.f;
                }
                ch = nch;
            }
            #pragma unroll
            for (int g = 0; g < 2; g++) {
                float4 v[4];
                #pragma unroll
                for (int j = 0; j < 4; j++)
                    v[j] = *(const float4*)(rbase + (size_t)(2 * (4 * g + j)) * KTOT + kb);
                #pragma unroll
                for (int j = 0; j < 4; j++) {
                    accP[4 * g + j] += (v[j].x + v[j].y) + (v[j].z + v[j].w);
                    pf[4 * g + j] = cvt_bf16x4(v[j]);
                }
            }
        }

        const uint32_t base = smem_u32(&tile[0][0]);
        #pragma unroll
        for (int ks = 0; ks < 4; ks++) {
            const int kc = ks * 16;
            uint32_t afr[4][4];
            #pragma unroll
            for (int mi = 0; mi < 4; mi++) {
                int r = mbase + mi * 16 + a_row;
                ldm4(afr[mi], base + (uint32_t)(r * LDPAD + kc + a_colo) * 2u);
            }
            #pragma unroll
            for (int nt = 0; nt < 2; nt++) {
                uint32_t b4[4];
                int r = nbase + nt * 16 + b_rowo;
                ldm4(b4, base + (uint32_t)(r * LDPAD + kc + b_colo) * 2u);
                #pragma unroll
                for (int mi = 0; mi < 4; mi++) {
                    mma16816(acc[mi][2 * nt],     afr[mi], b4[0], b4[1]);
                    mma16816(acc[mi][2 * nt + 1], afr[mi], b4[2], b4[3]);
                }
            }
        }
        __syncthreads();
    }

    #pragma unroll
    for (int i = 0; i < 8; i++)
        atomicAdd(&g_pool[mat][row0 + 2 * i][ch], accP[i]);

    const int mrow = lane >> 2;
    const int ncol = 2 * (lane & 3);
    #pragma unroll
    for (int mi = 0; mi < 4; mi++) {
        #pragma unroll
        for (int ni = 0; ni < 4; ni++) {
            int m = mbase + mi * 16 + mrow;
            int n = nbase + ni * 8 + ncol;
            atomicAdd(&g_gram[mat][m][n],         acc[mi][ni][0]);
            atomicAdd(&g_gram[mat][m][n + 1],     acc[mi][ni][1]);
            atomicAdd(&g_gram[mat][m + 8][n],     acc[mi][ni][2]);
            atomicAdd(&g_gram[mat][m + 8][n + 1], acc[mi][ni][3]);
        }
    }
}

// ---------------------------------------------------------------------------
// Kernel 2a: normalize + z (once).  32 CTAs x 4 batch rows.
//   Writes g_zs / g_zt for the MLP kernel.
// ---------------------------------------------------------------------------
__global__ __launch_bounds__(256)
void z_kernel() {
    __shared__ float ngs[4][128], ngt[4][128];
    __shared__ float redw[8];

    const int tid  = threadIdx.x;
    const int r0   = blockIdx.x * 4;
    const int half = tid >> 7;
    const int b    = tid & 127;

    for (int r = 0; r < 4; r++) {
        int rowi = r0 + r;
        float v = g_gram[half][rowi][b];
        float ss = v * v;
        #pragma unroll
        for (int o = 16; o; o >>= 1) ss += __shfl_xor_sync(0xFFFFFFFFu, ss, o);
        if ((tid & 31) == 0) redw[tid >> 5] = ss;
        __syncthreads();
        float nrm = sqrtf(redw[half * 4 + 0] + redw[half * 4 + 1] +
                          redw[half * 4 + 2] + redw[half * 4 + 3]);
        float inv = 1.f / fmaxf(nrm, 1e-12f);
        if (half) ngt[r][b] = v * inv; else ngs[r][b] = v * inv;
        __syncthreads();
    }

    const float inv784 = 1.f / 784.f;
    const int c = tid;
    float zs0 = 0, zs1 = 0, zs2 = 0, zs3 = 0;
    for (int bb = 0; bb < 128; bb++) {
        float yv = g_pool[0][bb][c] * inv784;
        zs0 += ngs[0][bb] * yv; zs1 += ngs[1][bb] * yv;
        zs2 += ngs[2][bb] * yv; zs3 += ngs[3][bb] * yv;
    }
    float zt0 = 0, zt1 = 0, zt2 = 0, zt3 = 0;
    for (int bb = 0; bb < 128; bb++) {
        float yv = g_pool[1][bb][c] * inv784;
        zt0 += ngt[0][bb] * yv; zt1 += ngt[1][bb] * yv;
        zt2 += ngt[2][bb] * yv; zt3 += ngt[3][bb] * yv;
    }
    g_zs[r0 + 0][c] = zs0; g_zs[r0 + 1][c] = zs1;
    g_zs[r0 + 2][c] = zs2; g_zs[r0 + 3][c] = zs3;
    g_zt[r0 + 0][c] = zt0; g_zt[r0 + 1][c] = zt1;
    g_zt[r0 + 2][c] = zt2; g_zt[r0 + 3][c] = zt3;
}

// ---------------------------------------------------------------------------
// Kernel 2b: ONE MLP per CTA -> atomicAdd into gates.
//   grid (32, 6): blockIdx.x = 4-row group, blockIdx.y = which MLP.
// ---------------------------------------------------------------------------
template <int DIN, int DH, int DOUT, int MAT>
__device__ __forceinline__ void run_mlp2(
    const float* __restrict__ w1, const float* __restrict__ b1,
    const float* __restrict__ w2, const float* __restrict__ b2,
    const float* zin /*[4][zstride]*/, int zstride,
    float* hb /*[4][128] flat*/, int r0, int tid)
{
    if (tid < DH) {
        const float4* wr = (const float4*)(w1 + (size_t)tid * DIN);
        float a0 = b1[tid], a1 = b1[tid], a2 = b1[tid], a3 = b1[tid];
        #pragma unroll 8
        for (int i4 = 0; i4 < DIN / 4; i4++) {
            float4 w = wr[i4];
            const float* z0 = zin + 4 * i4;
            a0 += z0[0] * w.x + z0[1] * w.y + z0[2] * w.z + z0[3] * w.w;
            const float* z1 = z0 + zstride;
            a1 += z1[0] * w.x + z1[1] * w.y + z1[2] * w.z + z1[3] * w.w;
            const float* z2 = z1 + zstride;
            a2 += z2[0] * w.x + z2[1] * w.y + z2[2] * w.z + z2[3] * w.w;
            const float* z3 = z2 + zstride;
            a3 += z3[0] * w.x + z3[1] * w.y + z3[2] * w.z + z3[3] * w.w;
        }
        hb[0 * 128 + tid] = fmaxf(a0, 0.f);
        hb[1 * 128 + tid] = fmaxf(a1, 0.f);
        hb[2 * 128 + tid] = fmaxf(a2, 0.f);
        hb[3 * 128 + tid] = fmaxf(a3, 0.f);
    }
    __syncthreads();
    {
        const float4* wr = (const float4*)(w2 + (size_t)tid * DH);
        float a0 = b2[tid], a1 = b2[tid], a2 = b2[tid], a3 = b2[tid];
        #pragma unroll 8
        for (int i4 = 0; i4 < DH / 4; i4++) {
            float4 w = wr[i4];
            const float* h0 = hb + 4 * i4;
            a0 += h0[0] * w.x + h0[1] * w.y + h0[2] * w.z + h0[3] * w.w;
            const float* h1 = h0 + 128;
            a1 += h1[0] * w.x + h1[1] * w.y + h1[2] * w.z + h1[3] * w.w;
            const float* h2 = h1 + 128;
            a2 += h2[0] * w.x + h2[1] * w.y + h2[2] * w.z + h2[3] * w.w;
            const float* h3 = h2 + 128;
            a3 += h3[0] * w.x + h3[1] * w.y + h3[2] * w.z + h3[3] * w.w;
        }
        // relu(sigmoid(x)) == sigmoid(x); gates sum three sigmoids
        atomicAdd(&g_gate[MAT][r0 + 0][tid], 1.f / (1.f + expf(-a0)));
        atomicAdd(&g_gate[MAT][r0 + 1][tid], 1.f / (1.f + expf(-a1)));
        atomicAdd(&g_gate[MAT][r0 + 2][tid], 1.f / (1.f + expf(-a2)));
        atomicAdd(&g_gate[MAT][r0 + 3][tid], 1.f / (1.f + expf(-a3)));
    }
}

__global__ __launch_bounds__(256)
void mlp_kernel(
    const float* __restrict__ fs_w1,  const float* __restrict__ fs_b1,
    const float* __restrict__ fs_w2,  const float* __restrict__ fs_b2,
    const float* __restrict__ fsa_w1, const float* __restrict__ fsa_b1,
    const float* __restrict__ fsa_w2, const float* __restrict__ fsa_b2,
    const float* __restrict__ fsm_w1, const float* __restrict__ fsm_b1,
    const float* __restrict__ fsm_w2, const float* __restrict__ fsm_b2,
    const float* __restrict__ ft_w1,  const float* __restrict__ ft_b1,
    const float* __restrict__ ft_w2,  const float* __restrict__ ft_b2,
    const float* __restrict__ fta_w1, const float* __restrict__ fta_b1,
    const float* __restrict__ fta_w2, const float* __restrict__ fta_b2,
    const float* __restrict__ ftm_w1, const float* __restrict__ ftm_b1,
    const float* __restrict__ ftm_w2, const float* __restrict__ ftm_b2)
{
    __shared__ float zc[4][512];
    __shared__ float za[4][256], zm[4][256];
    __shared__ float hbuf[4][128];

    const int tid = threadIdx.x;
    const int r0  = blockIdx.x * 4;
    const int c   = tid;

    #pragma unroll
    for (int r = 0; r < 4; r++) {
        float zs = g_zs[r0 + r][c];
        float zt = g_zt[r0 + r][c];
        zc[r][c] = zs; zc[r][256 + c] = zt;
        za[r][c] = zs + zt; zm[r][c] = zs * zt;
    }
    __syncthreads();

    switch (blockIdx.y) {
    case 0: run_mlp2<512, 128, 256, 0>(fs_w1, fs_b1, fs_w2, fs_b2,
                &zc[0][0], 512, &hbuf[0][0], r0, tid); break;
    case 1: run_mlp2<256, 64, 256, 0>(fsa_w1, fsa_b1, fsa_w2, fsa_b2,
                &za[0][0], 256, &hbuf[0][0], r0, tid); break;
    case 2: run_mlp2<256, 64, 256, 0>(fsm_w1, fsm_b1, fsm_w2, fsm_b2,
                &zm[0][0], 256, &hbuf[0][0], r0, tid); break;
    case 3: run_mlp2<512, 128, 256, 1>(ft_w1, ft_b1, ft_w2, ft_b2,
                &zc[0][0], 512, &hbuf[0][0], r0, tid); break;
    case 4: run_mlp2<256, 64, 256, 1>(fta_w1, fta_b1, fta_w2, fta_b2,
                &za[0][0], 256, &hbuf[0][0], r0, tid); break;
    case 5: run_mlp2<256, 64, 256, 1>(ftm_w1, ftm_b1, ftm_w2, ftm_b2,
                &zm[0][0], 256, &hbuf[0][0], r0, tid); break;
    }
}

// ---------------------------------------------------------------------------
// Kernel 3: out = gate ⊙ x  (both tensors; float4 granularity)
// ---------------------------------------------------------------------------
#define PERQ 6422528            // float4 per tensor (128*256*784/4)
__global__ __launch_bounds__(256)
void scale_kernel(const float4* __restrict__ s, const float4* __restrict__ t,
                  float4* __restrict__ out) {
    unsigned idx = blockIdx.x * 256u + threadIdx.x;
    int m = idx >= PERQ;
    unsigned j = idx - (unsigned)m * PERQ;
    unsigned bc = j / 196u;                            // 196 float4 per (b,c)
    float g = g_gate[m][bc >> 8][bc & 255];
    float4 v = m ? t[j] : s[j];
    out[idx] = make_float4(g * v.x, g * v.y, g * v.z, g * v.w);
}

// ---------------------------------------------------------------------------
// Launch
// ---------------------------------------------------------------------------
extern "C" void kernel_launch(void* const* d_in, const int* in_sizes, int n_in,
                              void* d_out, int out_size) {
    const float* s = (const float*)d_in[0];
    const float* t = (const float*)d_in[1];
    const float* w[24];
    for (int i = 0; i < 24; i++) w[i] = (const float*)d_in[2 + i];

    zero_kernel<<<256, 256>>>();
    gram_kernel<<<dim3(GRIDX, 2), 256>>>(s, t);
    z_kernel<<<32, 256>>>();
    mlp_kernel<<<dim3(32, 6), 256>>>(
        w[0],  w[1],  w[2],  w[3],
        w[4],  w[5],  w[6],  w[7],
        w[8],  w[9],  w[10], w[11],
        w[12], w[13], w[14], w[15],
        w[16], w[17], w[18], w[19],
        w[20], w[21], w[22], w[23]);
    scale_kernel<<<(2 * PERQ) / 256, 256>>>((const float4*)s, (const float4*)t,
                                            (float4*)d_out);
}